// round 5
// baseline (speedup 1.0000x reference)
#include <cuda_runtime.h>
#include <math.h>

#define CCH   64
#define PIX   262144
#define NCLS  11
#define GRIDP 128     // kprep: stride 128*512 = 65536 divides PIX exactly (ballot-safe)
#define GRID  148
#define NTHR  512

// ---------------- device-global scratch (no allocation) ----------------
__device__ unsigned short g_pm[PIX];            // packed 16-bit instance masks
__device__ float g_invn[PIX];                   // 1/||X2_p||
__device__ int   g_pcnt[GRIDP][16];             // per-block mask counts
__device__ __align__(16) float g_p1[GRID][1040]; // [k*64+c] pcs, [1024+k] sumsq
__device__ __align__(16) float g_p2[GRID][1024]; // Z[k*64+c]

// ---------------- f32x2 helpers ----------------
__device__ __forceinline__ unsigned long long pack2(float lo, float hi) {
    unsigned long long r;
    asm("mov.b64 %0, {%1, %2};" : "=l"(r) : "f"(lo), "f"(hi));
    return r;
}
__device__ __forceinline__ float2 unpack2(unsigned long long v) {
    float2 f;
    asm("mov.b64 {%0, %1}, %2;" : "=f"(f.x), "=f"(f.y) : "l"(v));
    return f;
}
__device__ __forceinline__ unsigned long long addf2(unsigned long long a, unsigned long long b) {
    unsigned long long r;
    asm("add.rn.f32x2 %0, %1, %2;" : "=l"(r) : "l"(a), "l"(b));
    return r;
}
__device__ __forceinline__ unsigned long long mulf2(unsigned long long a, unsigned long long b) {
    unsigned long long r;
    asm("mul.rn.f32x2 %0, %1, %2;" : "=l"(r) : "l"(a), "l"(b));
    return r;
}
// predicated masked accumulate: if (b) { a01+=x01; a23+=x23; q+=s2; }  (no branches)
__device__ __forceinline__ void macc3(unsigned long long &a01, unsigned long long &a23,
                                      float &q, unsigned long long x01, unsigned long long x23,
                                      float s2, unsigned b) {
    asm("{ .reg .pred p;\n\t"
        "setp.ne.u32 p, %6, 0;\n\t"
        "@p add.rn.f32x2 %0, %0, %3;\n\t"
        "@p add.rn.f32x2 %1, %1, %4;\n\t"
        "@p add.f32 %2, %2, %5; }"
        : "+l"(a01), "+l"(a23), "+f"(q)
        : "l"(x01), "l"(x23), "f"(s2), "r"(b));
}
__device__ __forceinline__ void macc2(unsigned long long &a01, unsigned long long &a23,
                                      unsigned long long x01, unsigned long long x23,
                                      unsigned b) {
    asm("{ .reg .pred p;\n\t"
        "setp.ne.u32 p, %4, 0;\n\t"
        "@p add.rn.f32x2 %0, %0, %2;\n\t"
        "@p add.rn.f32x2 %1, %1, %3; }"
        : "+l"(a01), "+l"(a23)
        : "l"(x01), "l"(x23), "r"(b));
}

// ---------------- kprep: pack masks, counts, X2 inverse norms ----------------
__global__ __launch_bounds__(NTHR, 1) void kprep(const int* __restrict__ masks,
                                                 const float* __restrict__ X2) {
    __shared__ int s_cnt[16][16];
    int tid = threadIdx.x, lane = tid & 31, w = tid >> 5;
    int gt = blockIdx.x * NTHR + tid;
    const int stride = GRIDP * NTHR;  // 65536, divides PIX exactly

    int cnt = 0;
#pragma unroll
    for (int it = 0; it < PIX / (GRIDP * NTHR); it++) {   // exactly 4 uniform iters
        int p = gt + it * stride;
        unsigned pm = 0;
#pragma unroll
        for (int k = 0; k < 16; k++)
            pm |= (masks[k * PIX + p] == 1) ? (1u << k) : 0u;
        g_pm[p] = (unsigned short)pm;
#pragma unroll
        for (int k = 0; k < 16; k++) {
            unsigned bal = __ballot_sync(0xffffffffu, (pm >> k) & 1u);
            cnt += (lane == k) ? __popc(bal) : 0;
        }
    }
    if (lane < 16) s_cnt[w][lane] = cnt;

    // X2 inverse norms: 4 pixels per thread (float4), one pass over 64 channels
    {
        const float4* X2v = (const float4*)X2;
        int q4 = gt;  // PIX/4 == 65536 == stride → exactly one quad per thread
        float4 n2 = make_float4(0.f, 0.f, 0.f, 0.f);
#pragma unroll 8
        for (int c = 0; c < CCH; c++) {
            float4 x = X2v[(size_t)c * (PIX / 4) + q4];
            n2.x = fmaf(x.x, x.x, n2.x);
            n2.y = fmaf(x.y, x.y, n2.y);
            n2.z = fmaf(x.z, x.z, n2.z);
            n2.w = fmaf(x.w, x.w, n2.w);
        }
        float4 inv;
        inv.x = rsqrtf(n2.x); inv.y = rsqrtf(n2.y);
        inv.z = rsqrtf(n2.z); inv.w = rsqrtf(n2.w);
        ((float4*)g_invn)[q4] = inv;
    }
    __syncthreads();
    if (tid < 16) {
        int s = 0;
#pragma unroll
        for (int w2 = 0; w2 < 16; w2++) s += s_cnt[w2][tid];
        g_pcnt[blockIdx.x][tid] = s;
    }
}

// ---------------- k1: masked per-channel sums of X1 + sumsq ----------------
__global__ __launch_bounds__(NTHR, 1) void k1(const float* __restrict__ X1) {
    __shared__ float s_q[16][17];
    int tid = threadIdx.x, lane = tid & 31, w = tid >> 5;
    int cb = w * 4;

    unsigned long long a01[16], a23[16];
    float q[16];
#pragma unroll
    for (int k = 0; k < 16; k++) { a01[k] = 0ull; a23[k] = 0ull; q[k] = 0.f; }

    const float* b0 = X1 + (size_t)(cb + 0) * PIX;
    const float* b1 = X1 + (size_t)(cb + 1) * PIX;
    const float* b2 = X1 + (size_t)(cb + 2) * PIX;
    const float* b3 = X1 + (size_t)(cb + 3) * PIX;

    const int NG = PIX / 32;  // 8192
    int g = blockIdx.x;
    int p = g * 32 + lane;
    unsigned pmc = g_pm[p];
    float c0 = b0[p], c1 = b1[p], c2 = b2[p], c3 = b3[p];

    for (; g < NG; ) {
        int gn = g + GRID;
        unsigned pmn = 0;
        float n0 = 0.f, n1 = 0.f, n2 = 0.f, n3 = 0.f;
        if (gn < NG) {  // uniform branch (g identical across block)
            int pn = gn * 32 + lane;
            pmn = g_pm[pn];
            n0 = b0[pn]; n1 = b1[pn]; n2 = b2[pn]; n3 = b3[pn];
        }
        unsigned long long X01 = pack2(c0, c1);
        unsigned long long X23 = pack2(c2, c3);
        float s2 = fmaf(c0, c0, fmaf(c1, c1, fmaf(c2, c2, c3 * c3)));
#pragma unroll
        for (int k = 0; k < 16; k++)
            macc3(a01[k], a23[k], q[k], X01, X23, s2, pmc & (1u << k));
        pmc = pmn; c0 = n0; c1 = n1; c2 = n2; c3 = n3;
        g = gn;
    }

#pragma unroll
    for (int k = 0; k < 16; k++) {
#pragma unroll
        for (int s = 16; s > 0; s >>= 1) {
            a01[k] = addf2(a01[k], __shfl_xor_sync(0xffffffffu, a01[k], s));
            a23[k] = addf2(a23[k], __shfl_xor_sync(0xffffffffu, a23[k], s));
            q[k] += __shfl_xor_sync(0xffffffffu, q[k], s);
        }
    }
    if (lane == 0) {
#pragma unroll
        for (int k = 0; k < 16; k++) {
            float2 u = unpack2(a01[k]), v = unpack2(a23[k]);
            *(float4*)&g_p1[blockIdx.x][k * 64 + cb] = make_float4(u.x, u.y, v.x, v.y);
            s_q[w][k] = q[k];
        }
    }
    __syncthreads();
    if (tid < 16) {
        float s = 0.f;
#pragma unroll
        for (int w2 = 0; w2 < 16; w2++) s += s_q[w2][tid];
        g_p1[blockIdx.x][1024 + tid] = s;
    }
}

// ---------------- k4: masked per-channel sums of normalized X2 (Z) ----------------
__global__ __launch_bounds__(NTHR, 1) void k4(const float* __restrict__ X2) {
    int tid = threadIdx.x, lane = tid & 31, w = tid >> 5;
    int cb = w * 4;

    unsigned long long a01[16], a23[16];
#pragma unroll
    for (int k = 0; k < 16; k++) { a01[k] = 0ull; a23[k] = 0ull; }

    const float* b0 = X2 + (size_t)(cb + 0) * PIX;
    const float* b1 = X2 + (size_t)(cb + 1) * PIX;
    const float* b2 = X2 + (size_t)(cb + 2) * PIX;
    const float* b3 = X2 + (size_t)(cb + 3) * PIX;

    const int NG = PIX / 32;
    int g = blockIdx.x;
    int p = g * 32 + lane;
    unsigned pmc = g_pm[p];
    float ivc = g_invn[p];
    float c0 = b0[p], c1 = b1[p], c2 = b2[p], c3 = b3[p];

    for (; g < NG; ) {
        int gn = g + GRID;
        unsigned pmn = 0;
        float iv_n = 0.f, n0 = 0.f, n1 = 0.f, n2 = 0.f, n3 = 0.f;
        if (gn < NG) {
            int pn = gn * 32 + lane;
            pmn = g_pm[pn]; iv_n = g_invn[pn];
            n0 = b0[pn]; n1 = b1[pn]; n2 = b2[pn]; n3 = b3[pn];
        }
        unsigned long long iv2 = pack2(ivc, ivc);
        unsigned long long Y01 = mulf2(pack2(c0, c1), iv2);
        unsigned long long Y23 = mulf2(pack2(c2, c3), iv2);
#pragma unroll
        for (int k = 0; k < 16; k++)
            macc2(a01[k], a23[k], Y01, Y23, pmc & (1u << k));
        pmc = pmn; ivc = iv_n; c0 = n0; c1 = n1; c2 = n2; c3 = n3;
        g = gn;
    }

#pragma unroll
    for (int k = 0; k < 16; k++) {
#pragma unroll
        for (int s = 16; s > 0; s >>= 1) {
            a01[k] = addf2(a01[k], __shfl_xor_sync(0xffffffffu, a01[k], s));
            a23[k] = addf2(a23[k], __shfl_xor_sync(0xffffffffu, a23[k], s));
        }
    }
    if (lane == 0) {
#pragma unroll
        for (int k = 0; k < 16; k++) {
            float2 u = unpack2(a01[k]), v = unpack2(a23[k]);
            *(float4*)&g_p2[blockIdx.x][k * 64 + cb] = make_float4(u.x, u.y, v.x, v.y);
        }
    }
}

// ---------------- kfinal: reduce + stats + sim + class/bucket outputs ----------------
__device__ __forceinline__ bool gpred(int b, int l) {
    if (b == 0) return (l >= 1) && (l <= 8);
    if (b == 1) return (l >= 3) && (l <= 10);
    return ((l >= 1) && (l <= 2)) || ((l >= 9) && (l <= 10));
}

__global__ void kfinal(const int* __restrict__ labels, float* __restrict__ out) {
    __shared__ float s_mean[1024];   // pcs -> means (in place)
    __shared__ float s_Z[1024];
    __shared__ float s_q[16], s_cntraw[16], s_cnt[16], s_nm[16], s_std[16];
    __shared__ float s_sim[256];
    __shared__ int s_lab[16];
    int tid = threadIdx.x;

    // reduce 148-block partials (unrolled by 4: 148 = 4*37)
    for (int v = tid; v < 1024; v += NTHR) {
        float r0 = 0.f, r1 = 0.f, r2 = 0.f, r3 = 0.f;
        for (int b = 0; b < GRID; b += 4) {
            r0 += g_p1[b][v]; r1 += g_p1[b + 1][v];
            r2 += g_p1[b + 2][v]; r3 += g_p1[b + 3][v];
        }
        s_mean[v] = (r0 + r1) + (r2 + r3);
    }
    for (int v = tid; v < 1024; v += NTHR) {
        float r0 = 0.f, r1 = 0.f, r2 = 0.f, r3 = 0.f;
        for (int b = 0; b < GRID; b += 4) {
            r0 += g_p2[b][v]; r1 += g_p2[b + 1][v];
            r2 += g_p2[b + 2][v]; r3 += g_p2[b + 3][v];
        }
        s_Z[v] = (r0 + r1) + (r2 + r3);
    }
    if (tid < 16) {
        float s = 0.f;
        for (int b = 0; b < GRID; b++) s += g_p1[b][1024 + tid];
        s_q[tid] = s;
    }
    if (tid >= 32 && tid < 48) {
        int k = tid - 32, s = 0;
        for (int b = 0; b < GRIDP; b++) s += g_pcnt[b][k];
        s_cntraw[k] = (float)s;
    }
    if (tid >= 64 && tid < 80) s_lab[tid - 64] = labels[tid - 64];
    __syncthreads();

    if (tid < 16) {
        int k = tid;
        float counts = s_cntraw[k];
        float cnt = fmaxf(counts, 1.f);
        float inv = 1.f / cnt;
        float sa = 0.f, nm2 = 0.f;
        for (int c = 0; c < 64; c++) {
            float pcs = s_mean[k * 64 + c];
            sa += pcs;
            float m = pcs * inv;
            s_mean[k * 64 + c] = m;
            nm2 = fmaf(m, m, nm2);
        }
        s_nm[k] = sqrtf(nm2);
        s_cnt[k] = cnt;
        float ne = counts * 64.f;
        float ma = sa / fmaxf(ne, 1.f);
        float var = (s_q[k] - ne * ma * ma) / fmaxf(ne - 1.f, 1.f);
        s_std[k] = sqrtf(fmaxf(var, 0.f));
    }
    __syncthreads();

    // sim[i][j] = (means_i . Z_j) / (nm_i * cnt_j)
    if (tid < 256) {
        int i = tid >> 4, j = tid & 15;
        float d = 0.f;
        for (int c = 0; c < 64; c++)
            d = fmaf(s_mean[i * 64 + c], s_Z[j * 64 + c], d);
        s_sim[tid] = d / (fmaxf(s_nm[i], 1e-20f) * s_cnt[j]);
    }
    __syncthreads();

    if (tid < NCLS) {
        int cl = tid;
        float cc = 0.f, inst = 0.f, cstd = 0.f, csim = 0.f;
        for (int k = 0; k < 16; k++) {
            if (s_lab[k] == cl) {
                cc += 1.f;
                inst += s_sim[k * 16 + k];
                cstd += s_std[k];
            }
        }
        for (int i = 0; i < 16; i++) {
            if (s_lab[i] != cl) continue;
            for (int j = 0; j < 16; j++)
                if (j != i && s_lab[j] == cl) csim += s_sim[i * 16 + j];
        }
        bool many = cc > 1.f;
        out[cl]      = many ? inst / fmaxf(cc, 1.f) : inst;
        out[11 + cl] = many ? csim / fmaxf(cc * (cc - 1.f), 1.f) : csim;
        out[25 + cl] = many ? cstd / fmaxf(cc, 1.f) : cstd;
    }
    if (tid >= 32 && tid < 35) {
        int b = tid - 32;
        float s = 0.f;
        int c = 0;
        for (int i = 0; i < 16; i++) {
            if (!gpred(b, s_lab[i])) continue;
            for (int j = 0; j < 16; j++) {
                if (s_lab[j] != s_lab[i] && gpred(b, s_lab[j])) {
                    c++;
                    s += s_sim[i * 16 + j];
                }
            }
        }
        out[22 + b] = (c > 1) ? s / (float)c : s;
    }
}

// ---------------- launcher ----------------
extern "C" void kernel_launch(void* const* d_in, const int* in_sizes, int n_in,
                              void* d_out, int out_size) {
    const float* v1     = (const float*)d_in[0];
    const float* v2     = (const float*)d_in[1];
    const int*   masks  = (const int*)d_in[2];
    const int*   labels = (const int*)d_in[3];
    float* out = (float*)d_out;

    kprep<<<GRIDP, NTHR>>>(masks, v2);
    k1<<<GRID, NTHR>>>(v1);
    k4<<<GRID, NTHR>>>(v2);
    kfinal<<<1, NTHR>>>(labels, out);
}

// round 6
// speedup vs baseline: 1.0847x; 1.0847x over previous
#include <cuda_runtime.h>
#include <math.h>

#define CCH   64
#define PIX   262144
#define NCLS  11
#define GRIDP 128
#define GRID  148
#define NTHR  512

// ---------------- device-global scratch (no allocation) ----------------
__device__ __align__(8) unsigned short g_pm[PIX];   // packed 16-bit instance masks
__device__ float g_invn[PIX];                       // 1/||X2_p||
__device__ int   g_pcnt[GRIDP][16];                 // per-block mask counts
__device__ __align__(16) float g_p1[GRID][1040];    // [k*64+c] pcs, [1024+k] sumsq
__device__ __align__(16) float g_p2[GRID][1024];    // Z partials
__device__ float g_red1[1040];
__device__ float g_red2[1024];
__device__ float g_redc[16];

// ---------------- f32x2 helpers ----------------
__device__ __forceinline__ unsigned long long pack2(float lo, float hi) {
    unsigned long long r;
    asm("mov.b64 %0, {%1, %2};" : "=l"(r) : "f"(lo), "f"(hi));
    return r;
}
__device__ __forceinline__ float2 unpack2(unsigned long long v) {
    float2 f;
    asm("mov.b64 {%0, %1}, %2;" : "=f"(f.x), "=f"(f.y) : "l"(v));
    return f;
}
__device__ __forceinline__ unsigned long long addf2(unsigned long long a, unsigned long long b) {
    unsigned long long r;
    asm("add.rn.f32x2 %0, %1, %2;" : "=l"(r) : "l"(a), "l"(b));
    return r;
}
__device__ __forceinline__ unsigned long long mulf2(unsigned long long a, unsigned long long b) {
    unsigned long long r;
    asm("mul.rn.f32x2 %0, %1, %2;" : "=l"(r) : "l"(a), "l"(b));
    return r;
}
__device__ __forceinline__ void macc3(unsigned long long &a01, unsigned long long &a23,
                                      float &q, unsigned long long x01, unsigned long long x23,
                                      float s2, unsigned b) {
    asm("{ .reg .pred p;\n\t"
        "setp.ne.u32 p, %6, 0;\n\t"
        "@p add.rn.f32x2 %0, %0, %3;\n\t"
        "@p add.rn.f32x2 %1, %1, %4;\n\t"
        "@p add.f32 %2, %2, %5; }"
        : "+l"(a01), "+l"(a23), "+f"(q)
        : "l"(x01), "l"(x23), "f"(s2), "r"(b));
}
__device__ __forceinline__ void macc2(unsigned long long &a01, unsigned long long &a23,
                                      unsigned long long x01, unsigned long long x23,
                                      unsigned b) {
    asm("{ .reg .pred p;\n\t"
        "setp.ne.u32 p, %4, 0;\n\t"
        "@p add.rn.f32x2 %0, %0, %2;\n\t"
        "@p add.rn.f32x2 %1, %1, %3; }"
        : "+l"(a01), "+l"(a23)
        : "l"(x01), "l"(x23), "r"(b));
}

// ---------------- kprep: pack masks (values are 0/1), counts, X2 inverse norms ----
__global__ __launch_bounds__(NTHR, 1) void kprep(const int* __restrict__ masks,
                                                 const float* __restrict__ X2) {
    __shared__ int s_cnt[16][16];
    int tid = threadIdx.x, lane = tid & 31, w = tid >> 5;
    int q4 = blockIdx.x * NTHR + tid;   // quad index; GRIDP*NTHR == PIX/4 exactly

    const int4* m4 = (const int4*)masks;
    unsigned pm0 = 0, pm1 = 0, pm2 = 0, pm3 = 0;
    int cnt[16];
#pragma unroll
    for (int k = 0; k < 16; k++) cnt[k] = 0;
#pragma unroll
    for (int k = 0; k < 16; k++) {
        int4 v = m4[(size_t)k * (PIX / 4) + q4];   // mask values are 0 or 1
        pm0 |= (unsigned)v.x << k;
        pm1 |= (unsigned)v.y << k;
        pm2 |= (unsigned)v.z << k;
        pm3 |= (unsigned)v.w << k;
        cnt[k] = (v.x + v.y) + (v.z + v.w);
    }
    {
        ushort4 st;
        st.x = (unsigned short)pm0; st.y = (unsigned short)pm1;
        st.z = (unsigned short)pm2; st.w = (unsigned short)pm3;
        ((ushort4*)g_pm)[q4] = st;
    }
    // warp-reduce counts
#pragma unroll
    for (int k = 0; k < 16; k++) {
#pragma unroll
        for (int s = 16; s > 0; s >>= 1)
            cnt[k] += __shfl_xor_sync(0xffffffffu, cnt[k], s);
    }
    if (lane < 16) s_cnt[w][lane] = cnt[lane];

    // X2 inverse norms for the same quad
    {
        const float4* X2v = (const float4*)X2;
        float4 n2 = make_float4(0.f, 0.f, 0.f, 0.f);
#pragma unroll 8
        for (int c = 0; c < CCH; c++) {
            float4 x = X2v[(size_t)c * (PIX / 4) + q4];
            n2.x = fmaf(x.x, x.x, n2.x);
            n2.y = fmaf(x.y, x.y, n2.y);
            n2.z = fmaf(x.z, x.z, n2.z);
            n2.w = fmaf(x.w, x.w, n2.w);
        }
        float4 inv;
        inv.x = rsqrtf(n2.x); inv.y = rsqrtf(n2.y);
        inv.z = rsqrtf(n2.z); inv.w = rsqrtf(n2.w);
        ((float4*)g_invn)[q4] = inv;
    }
    __syncthreads();
    if (tid < 16) {
        int s = 0;
#pragma unroll
        for (int w2 = 0; w2 < 16; w2++) s += s_cnt[w2][tid];
        g_pcnt[blockIdx.x][tid] = s;
    }
}

// ---------------- k1: masked per-channel sums of X1 + sumsq ----------------
__global__ __launch_bounds__(NTHR, 1) void k1(const float* __restrict__ X1) {
    __shared__ float s_q[16][17];
    int tid = threadIdx.x, lane = tid & 31, w = tid >> 5;
    int cb = w * 4;

    unsigned long long a01[16], a23[16];
    float q[16];
#pragma unroll
    for (int k = 0; k < 16; k++) { a01[k] = 0ull; a23[k] = 0ull; q[k] = 0.f; }

    const float* b0 = X1 + (size_t)(cb + 0) * PIX;
    const float* b1 = X1 + (size_t)(cb + 1) * PIX;
    const float* b2 = X1 + (size_t)(cb + 2) * PIX;
    const float* b3 = X1 + (size_t)(cb + 3) * PIX;

    const int NG = PIX / 32;  // 8192
    int g = blockIdx.x;
    int p = g * 32 + lane;
    unsigned pmc = g_pm[p];
    float c0 = b0[p], c1 = b1[p], c2 = b2[p], c3 = b3[p];

    for (; g < NG; ) {
        int gn = g + GRID;
        unsigned pmn = 0;
        float n0 = 0.f, n1 = 0.f, n2 = 0.f, n3 = 0.f;
        if (gn < NG) {  // uniform branch
            int pn = gn * 32 + lane;
            pmn = g_pm[pn];
            n0 = b0[pn]; n1 = b1[pn]; n2 = b2[pn]; n3 = b3[pn];
        }
        unsigned long long X01 = pack2(c0, c1);
        unsigned long long X23 = pack2(c2, c3);
        float s2 = fmaf(c0, c0, fmaf(c1, c1, fmaf(c2, c2, c3 * c3)));
#pragma unroll
        for (int k = 0; k < 16; k++)
            macc3(a01[k], a23[k], q[k], X01, X23, s2, pmc & (1u << k));
        pmc = pmn; c0 = n0; c1 = n1; c2 = n2; c3 = n3;
        g = gn;
    }

#pragma unroll
    for (int k = 0; k < 16; k++) {
#pragma unroll
        for (int s = 16; s > 0; s >>= 1) {
            a01[k] = addf2(a01[k], __shfl_xor_sync(0xffffffffu, a01[k], s));
            a23[k] = addf2(a23[k], __shfl_xor_sync(0xffffffffu, a23[k], s));
            q[k] += __shfl_xor_sync(0xffffffffu, q[k], s);
        }
    }
    if (lane == 0) {
#pragma unroll
        for (int k = 0; k < 16; k++) {
            float2 u = unpack2(a01[k]), v = unpack2(a23[k]);
            *(float4*)&g_p1[blockIdx.x][k * 64 + cb] = make_float4(u.x, u.y, v.x, v.y);
            s_q[w][k] = q[k];
        }
    }
    __syncthreads();
    if (tid < 16) {
        float s = 0.f;
#pragma unroll
        for (int w2 = 0; w2 < 16; w2++) s += s_q[w2][tid];
        g_p1[blockIdx.x][1024 + tid] = s;
    }
}

// ---------------- k4: masked per-channel sums of normalized X2 ----------------
__global__ __launch_bounds__(NTHR, 1) void k4(const float* __restrict__ X2) {
    int tid = threadIdx.x, lane = tid & 31, w = tid >> 5;
    int cb = w * 4;

    unsigned long long a01[16], a23[16];
#pragma unroll
    for (int k = 0; k < 16; k++) { a01[k] = 0ull; a23[k] = 0ull; }

    const float* b0 = X2 + (size_t)(cb + 0) * PIX;
    const float* b1 = X2 + (size_t)(cb + 1) * PIX;
    const float* b2 = X2 + (size_t)(cb + 2) * PIX;
    const float* b3 = X2 + (size_t)(cb + 3) * PIX;

    const int NG = PIX / 32;
    int g = blockIdx.x;
    int p = g * 32 + lane;
    unsigned pmc = g_pm[p];
    float ivc = g_invn[p];
    float c0 = b0[p], c1 = b1[p], c2 = b2[p], c3 = b3[p];

    for (; g < NG; ) {
        int gn = g + GRID;
        unsigned pmn = 0;
        float iv_n = 0.f, n0 = 0.f, n1 = 0.f, n2 = 0.f, n3 = 0.f;
        if (gn < NG) {
            int pn = gn * 32 + lane;
            pmn = g_pm[pn]; iv_n = g_invn[pn];
            n0 = b0[pn]; n1 = b1[pn]; n2 = b2[pn]; n3 = b3[pn];
        }
        unsigned long long iv2 = pack2(ivc, ivc);
        unsigned long long Y01 = mulf2(pack2(c0, c1), iv2);
        unsigned long long Y23 = mulf2(pack2(c2, c3), iv2);
#pragma unroll
        for (int k = 0; k < 16; k++)
            macc2(a01[k], a23[k], Y01, Y23, pmc & (1u << k));
        pmc = pmn; ivc = iv_n; c0 = n0; c1 = n1; c2 = n2; c3 = n3;
        g = gn;
    }

#pragma unroll
    for (int k = 0; k < 16; k++) {
#pragma unroll
        for (int s = 16; s > 0; s >>= 1) {
            a01[k] = addf2(a01[k], __shfl_xor_sync(0xffffffffu, a01[k], s));
            a23[k] = addf2(a23[k], __shfl_xor_sync(0xffffffffu, a23[k], s));
        }
    }
    if (lane == 0) {
#pragma unroll
        for (int k = 0; k < 16; k++) {
            float2 u = unpack2(a01[k]), v = unpack2(a23[k]);
            *(float4*)&g_p2[blockIdx.x][k * 64 + cb] = make_float4(u.x, u.y, v.x, v.y);
        }
    }
}

// ---------------- kred: parallel deterministic cross-block reduce ----------------
__global__ void kred() {
    int v = blockIdx.x * blockDim.x + threadIdx.x;  // <<<17,128>>> = 2176
    if (v < 1040) {
        float r0 = 0.f, r1 = 0.f, r2 = 0.f, r3 = 0.f;
        for (int b = 0; b < GRID; b += 4) {
            r0 += g_p1[b][v];     r1 += g_p1[b + 1][v];
            r2 += g_p1[b + 2][v]; r3 += g_p1[b + 3][v];
        }
        g_red1[v] = (r0 + r1) + (r2 + r3);
    } else if (v < 2064) {
        int u = v - 1040;
        float r0 = 0.f, r1 = 0.f, r2 = 0.f, r3 = 0.f;
        for (int b = 0; b < GRID; b += 4) {
            r0 += g_p2[b][u];     r1 += g_p2[b + 1][u];
            r2 += g_p2[b + 2][u]; r3 += g_p2[b + 3][u];
        }
        g_red2[u] = (r0 + r1) + (r2 + r3);
    } else if (v < 2080) {
        int k = v - 2064;
        int s0 = 0, s1 = 0, s2 = 0, s3 = 0;
        for (int b = 0; b < GRIDP; b += 4) {
            s0 += g_pcnt[b][k];     s1 += g_pcnt[b + 1][k];
            s2 += g_pcnt[b + 2][k]; s3 += g_pcnt[b + 3][k];
        }
        g_redc[k] = (float)((s0 + s1) + (s2 + s3));
    }
}

// ---------------- kfinal: stats + sim + class/bucket outputs ----------------
__device__ __forceinline__ bool gpred(int b, int l) {
    if (b == 0) return (l >= 1) && (l <= 8);
    if (b == 1) return (l >= 3) && (l <= 10);
    return ((l >= 1) && (l <= 2)) || ((l >= 9) && (l <= 10));
}

__global__ void kfinal(const int* __restrict__ labels, float* __restrict__ out) {
    __shared__ float s_mean[1024];
    __shared__ float s_Z[1024];
    __shared__ float s_cnt[16], s_nm[16], s_std[16];
    __shared__ float s_sim[256];
    __shared__ int s_lab[16];
    int tid = threadIdx.x;

    for (int v = tid; v < 1024; v += NTHR) {
        s_mean[v] = g_red1[v];
        s_Z[v] = g_red2[v];
    }
    if (tid >= 64 && tid < 80) s_lab[tid - 64] = labels[tid - 64];
    __syncthreads();

    if (tid < 16) {
        int k = tid;
        float counts = g_redc[k];
        float cnt = fmaxf(counts, 1.f);
        float inv = 1.f / cnt;
        float sa = 0.f, nm2 = 0.f;
        for (int c = 0; c < 64; c++) {
            float pcs = s_mean[k * 64 + c];
            sa += pcs;
            float m = pcs * inv;
            s_mean[k * 64 + c] = m;
            nm2 = fmaf(m, m, nm2);
        }
        s_nm[k] = sqrtf(nm2);
        s_cnt[k] = cnt;
        float ne = counts * 64.f;
        float ma = sa / fmaxf(ne, 1.f);
        float var = (g_red1[1024 + k] - ne * ma * ma) / fmaxf(ne - 1.f, 1.f);
        s_std[k] = sqrtf(fmaxf(var, 0.f));
    }
    __syncthreads();

    // sim[i][j] = (means_i . Z_j) / (nm_i * cnt_j)
    if (tid < 256) {
        int i = tid >> 4, j = tid & 15;
        float d = 0.f;
        for (int c = 0; c < 64; c++)
            d = fmaf(s_mean[i * 64 + c], s_Z[j * 64 + c], d);
        s_sim[tid] = d / (fmaxf(s_nm[i], 1e-20f) * s_cnt[j]);
    }
    __syncthreads();

    if (tid < NCLS) {
        int cl = tid;
        float cc = 0.f, inst = 0.f, cstd = 0.f, csim = 0.f;
        for (int k = 0; k < 16; k++) {
            if (s_lab[k] == cl) {
                cc += 1.f;
                inst += s_sim[k * 16 + k];
                cstd += s_std[k];
            }
        }
        for (int i = 0; i < 16; i++) {
            if (s_lab[i] != cl) continue;
            for (int j = 0; j < 16; j++)
                if (j != i && s_lab[j] == cl) csim += s_sim[i * 16 + j];
        }
        bool many = cc > 1.f;
        out[cl]      = many ? inst / fmaxf(cc, 1.f) : inst;
        out[11 + cl] = many ? csim / fmaxf(cc * (cc - 1.f), 1.f) : csim;
        out[25 + cl] = many ? cstd / fmaxf(cc, 1.f) : cstd;
    }
    if (tid >= 32 && tid < 35) {
        int b = tid - 32;
        float s = 0.f;
        int c = 0;
        for (int i = 0; i < 16; i++) {
            if (!gpred(b, s_lab[i])) continue;
            for (int j = 0; j < 16; j++) {
                if (s_lab[j] != s_lab[i] && gpred(b, s_lab[j])) {
                    c++;
                    s += s_sim[i * 16 + j];
                }
            }
        }
        out[22 + b] = (c > 1) ? s / (float)c : s;
    }
}

// ---------------- launcher ----------------
extern "C" void kernel_launch(void* const* d_in, const int* in_sizes, int n_in,
                              void* d_out, int out_size) {
    const float* v1     = (const float*)d_in[0];
    const float* v2     = (const float*)d_in[1];
    const int*   masks  = (const int*)d_in[2];
    const int*   labels = (const int*)d_in[3];
    float* out = (float*)d_out;

    kprep<<<GRIDP, NTHR>>>(masks, v2);
    k1<<<GRID, NTHR>>>(v1);
    k4<<<GRID, NTHR>>>(v2);
    kred<<<17, 128>>>();
    kfinal<<<1, NTHR>>>(labels, out);
}

// round 9
// speedup vs baseline: 1.3381x; 1.2337x over previous
#include <cuda_runtime.h>
#include <math.h>

#define CCH   64
#define PIX   262144
#define NCLS  11
#define GRIDP 128
#define GRID  148
#define NTHR  512
#define NG    (PIX / 32)      // 8192 pixel groups of 32
#define ITER2 28              // 2*28 = 56 = ceil(NG/GRID)

// ---------------- device-global scratch (no allocation) ----------------
__device__ __align__(8) unsigned short g_pm[PIX];    // packed 16-bit instance masks
__device__ int   g_pcntT[16][GRIDP];                 // counts, transposed
__device__ float g_p1T[1040][GRID];                  // transposed partials (pcs + sumsq)
__device__ float g_p2T[1024][GRID];                  // transposed Z partials
__device__ float g_red1[1040];
__device__ float g_red2[1024];
__device__ float g_redc[16];

// ---------------- f32x2 helpers ----------------
__device__ __forceinline__ unsigned long long pack2(float lo, float hi) {
    unsigned long long r;
    asm("mov.b64 %0, {%1, %2};" : "=l"(r) : "f"(lo), "f"(hi));
    return r;
}
__device__ __forceinline__ float2 unpack2(unsigned long long v) {
    float2 f;
    asm("mov.b64 {%0, %1}, %2;" : "=f"(f.x), "=f"(f.y) : "l"(v));
    return f;
}
__device__ __forceinline__ unsigned long long addf2(unsigned long long a, unsigned long long b) {
    unsigned long long r;
    asm("add.rn.f32x2 %0, %1, %2;" : "=l"(r) : "l"(a), "l"(b));
    return r;
}
__device__ __forceinline__ unsigned long long mulf2(unsigned long long a, unsigned long long b) {
    unsigned long long r;
    asm("mul.rn.f32x2 %0, %1, %2;" : "=l"(r) : "l"(a), "l"(b));
    return r;
}
__device__ __forceinline__ void macc3(unsigned long long &a01, unsigned long long &a23,
                                      float &q, unsigned long long x01, unsigned long long x23,
                                      float s2, unsigned b) {
    asm("{ .reg .pred p;\n\t"
        "setp.ne.u32 p, %6, 0;\n\t"
        "@p add.rn.f32x2 %0, %0, %3;\n\t"
        "@p add.rn.f32x2 %1, %1, %4;\n\t"
        "@p add.f32 %2, %2, %5; }"
        : "+l"(a01), "+l"(a23), "+f"(q)
        : "l"(x01), "l"(x23), "f"(s2), "r"(b));
}
__device__ __forceinline__ void macc2(unsigned long long &a01, unsigned long long &a23,
                                      unsigned long long x01, unsigned long long x23,
                                      unsigned b) {
    asm("{ .reg .pred p;\n\t"
        "setp.ne.u32 p, %4, 0;\n\t"
        "@p add.rn.f32x2 %0, %0, %2;\n\t"
        "@p add.rn.f32x2 %1, %1, %3; }"
        : "+l"(a01), "+l"(a23)
        : "l"(x01), "l"(x23), "r"(b));
}

// ---------------- kprep: pack masks (values are 0/1) + counts ----------------
__global__ __launch_bounds__(NTHR, 1) void kprep(const int* __restrict__ masks) {
    __shared__ int s_cnt[16][16];
    int tid = threadIdx.x, lane = tid & 31, w = tid >> 5;
    int q4 = blockIdx.x * NTHR + tid;   // quad index; GRIDP*NTHR == PIX/4 exactly

    const int4* m4 = (const int4*)masks;
    unsigned pm0 = 0, pm1 = 0, pm2 = 0, pm3 = 0;
    int cnt[16];
#pragma unroll
    for (int k = 0; k < 16; k++) {
        int4 v = m4[(size_t)k * (PIX / 4) + q4];
        pm0 |= (unsigned)v.x << k;
        pm1 |= (unsigned)v.y << k;
        pm2 |= (unsigned)v.z << k;
        pm3 |= (unsigned)v.w << k;
        cnt[k] = (v.x + v.y) + (v.z + v.w);
    }
    {
        ushort4 st;
        st.x = (unsigned short)pm0; st.y = (unsigned short)pm1;
        st.z = (unsigned short)pm2; st.w = (unsigned short)pm3;
        ((ushort4*)g_pm)[q4] = st;
    }
#pragma unroll
    for (int k = 0; k < 16; k++) {
#pragma unroll
        for (int s = 16; s > 0; s >>= 1)
            cnt[k] += __shfl_xor_sync(0xffffffffu, cnt[k], s);
    }
    if (lane < 16) s_cnt[w][lane] = cnt[lane];
    __syncthreads();
    if (tid < 16) {
        int s = 0;
#pragma unroll
        for (int w2 = 0; w2 < 16; w2++) s += s_cnt[w2][tid];
        g_pcntT[tid][blockIdx.x] = s;
    }
}

// ---------------- k1: masked per-channel sums of X1 + sumsq (depth-2 pipeline) ----
__global__ __launch_bounds__(NTHR, 1) void k1(const float* __restrict__ X1) {
    __shared__ float s_q[16][17];
    int tid = threadIdx.x, lane = tid & 31, w = tid >> 5;
    int cb = w * 4;

    unsigned long long a01[16], a23[16];
    float q[16];
#pragma unroll
    for (int k = 0; k < 16; k++) { a01[k] = 0ull; a23[k] = 0ull; q[k] = 0.f; }

    const float* b0 = X1 + (size_t)(cb + 0) * PIX;
    const float* b1 = X1 + (size_t)(cb + 1) * PIX;
    const float* b2 = X1 + (size_t)(cb + 2) * PIX;
    const float* b3 = X1 + (size_t)(cb + 3) * PIX;

    unsigned pmA, pmB;
    float A0, A1, A2, A3, B0, B1, B2, B3;
    int g = blockIdx.x;

#define LD1(G, PM, X0, X1r, X2r, X3r)                              \
    {                                                              \
        int gc = min((G), NG - 1);                                 \
        int p = gc * 32 + lane;                                    \
        PM = ((G) < NG) ? (unsigned)g_pm[p] : 0u;                  \
        X0 = b0[p]; X1r = b1[p]; X2r = b2[p]; X3r = b3[p];         \
    }
#define PROC1(PM, X0, X1r, X2r, X3r)                                        \
    {                                                                       \
        unsigned long long X01 = pack2(X0, X1r);                            \
        unsigned long long X23 = pack2(X2r, X3r);                           \
        float s2 = fmaf(X0, X0, fmaf(X1r, X1r, fmaf(X2r, X2r, X3r * X3r))); \
        _Pragma("unroll")                                                   \
        for (int k = 0; k < 16; k++)                                        \
            macc3(a01[k], a23[k], q[k], X01, X23, s2, PM & (1u << k));      \
    }

    LD1(g, pmA, A0, A1, A2, A3);
    LD1(g + GRID, pmB, B0, B1, B2, B3);
#pragma unroll 1
    for (int it = 0; it < ITER2; it++) {
        unsigned pmc = pmA; float c0 = A0, c1 = A1, c2 = A2, c3 = A3;
        LD1(g + 2 * GRID, pmA, A0, A1, A2, A3);
        PROC1(pmc, c0, c1, c2, c3);
        pmc = pmB; c0 = B0; c1 = B1; c2 = B2; c3 = B3;
        LD1(g + 3 * GRID, pmB, B0, B1, B2, B3);
        PROC1(pmc, c0, c1, c2, c3);
        g += 2 * GRID;
    }

#pragma unroll
    for (int k = 0; k < 16; k++) {
#pragma unroll
        for (int s = 16; s > 0; s >>= 1) {
            a01[k] = addf2(a01[k], __shfl_xor_sync(0xffffffffu, a01[k], s));
            a23[k] = addf2(a23[k], __shfl_xor_sync(0xffffffffu, a23[k], s));
            q[k] += __shfl_xor_sync(0xffffffffu, q[k], s);
        }
    }
    if (lane == 0) {
#pragma unroll
        for (int k = 0; k < 16; k++) {
            float2 u = unpack2(a01[k]), v = unpack2(a23[k]);
            g_p1T[k * 64 + cb + 0][blockIdx.x] = u.x;
            g_p1T[k * 64 + cb + 1][blockIdx.x] = u.y;
            g_p1T[k * 64 + cb + 2][blockIdx.x] = v.x;
            g_p1T[k * 64 + cb + 3][blockIdx.x] = v.y;
            s_q[w][k] = q[k];
        }
    }
    __syncthreads();
    if (tid < 16) {
        float s = 0.f;
#pragma unroll
        for (int w2 = 0; w2 < 16; w2++) s += s_q[w2][tid];
        g_p1T[1024 + tid][blockIdx.x] = s;
    }
}

// ---------------- k4: masked sums of normalized X2, norms fused in-kernel ----------
__global__ __launch_bounds__(NTHR, 1) void k4(const float* __restrict__ X2) {
    __shared__ float s_sq[2][16][32];
    int tid = threadIdx.x, lane = tid & 31, w = tid >> 5;
    int cb = w * 4;

    unsigned long long a01[16], a23[16];
#pragma unroll
    for (int k = 0; k < 16; k++) { a01[k] = 0ull; a23[k] = 0ull; }

    const float* b0 = X2 + (size_t)(cb + 0) * PIX;
    const float* b1 = X2 + (size_t)(cb + 1) * PIX;
    const float* b2 = X2 + (size_t)(cb + 2) * PIX;
    const float* b3 = X2 + (size_t)(cb + 3) * PIX;

    unsigned pmA, pmB;
    float A0, A1, A2, A3, B0, B1, B2, B3;
    int g = blockIdx.x;

#define PROC2(BUF, PM, C0, C1, C2, C3)                                      \
    {                                                                       \
        float n2 = 0.f;                                                     \
        _Pragma("unroll")                                                   \
        for (int w2 = 0; w2 < 16; w2++) n2 += s_sq[BUF][w2][lane];          \
        float inv = rsqrtf(n2);                                             \
        unsigned long long iv2 = pack2(inv, inv);                           \
        unsigned long long Y01 = mulf2(pack2(C0, C1), iv2);                 \
        unsigned long long Y23 = mulf2(pack2(C2, C3), iv2);                 \
        _Pragma("unroll")                                                   \
        for (int k = 0; k < 16; k++)                                        \
            macc2(a01[k], a23[k], Y01, Y23, PM & (1u << k));                \
    }

    LD1(g, pmA, A0, A1, A2, A3);
    LD1(g + GRID, pmB, B0, B1, B2, B3);
#pragma unroll 1
    for (int it = 0; it < ITER2; it++) {
        // ---- phase A (buffer 0) ----
        {
            unsigned pmc = pmA; float c0 = A0, c1 = A1, c2 = A2, c3 = A3;
            s_sq[0][w][lane] = fmaf(c0, c0, fmaf(c1, c1, fmaf(c2, c2, c3 * c3)));
            LD1(g + 2 * GRID, pmA, A0, A1, A2, A3);   // refill A (overlaps barrier)
            __syncthreads();
            PROC2(0, pmc, c0, c1, c2, c3);
        }
        // ---- phase B (buffer 1) ----
        {
            unsigned pmc = pmB; float c0 = B0, c1 = B1, c2 = B2, c3 = B3;
            s_sq[1][w][lane] = fmaf(c0, c0, fmaf(c1, c1, fmaf(c2, c2, c3 * c3)));
            LD1(g + 3 * GRID, pmB, B0, B1, B2, B3);   // refill B
            __syncthreads();
            PROC2(1, pmc, c0, c1, c2, c3);
        }
        g += 2 * GRID;
    }

#pragma unroll
    for (int k = 0; k < 16; k++) {
#pragma unroll
        for (int s = 16; s > 0; s >>= 1) {
            a01[k] = addf2(a01[k], __shfl_xor_sync(0xffffffffu, a01[k], s));
            a23[k] = addf2(a23[k], __shfl_xor_sync(0xffffffffu, a23[k], s));
        }
    }
    if (lane == 0) {
#pragma unroll
        for (int k = 0; k < 16; k++) {
            float2 u = unpack2(a01[k]), v = unpack2(a23[k]);
            g_p2T[k * 64 + cb + 0][blockIdx.x] = u.x;
            g_p2T[k * 64 + cb + 1][blockIdx.x] = u.y;
            g_p2T[k * 64 + cb + 2][blockIdx.x] = v.x;
            g_p2T[k * 64 + cb + 3][blockIdx.x] = v.y;
        }
    }
}

// ---------------- kred: warp-per-value coalesced reduce ----------------
__global__ __launch_bounds__(NTHR, 1) void kred() {
    int lane = threadIdx.x & 31;
    int v = blockIdx.x * 16 + (threadIdx.x >> 5);   // <<<130,512>>> -> 2080 warps
    if (v < 1040) {
        const float* row = g_p1T[v];
        float s = 0.f;
#pragma unroll
        for (int i = 0; i < 5; i++) {
            int idx = lane + i * 32;
            s += (idx < GRID) ? row[idx] : 0.f;
        }
#pragma unroll
        for (int sh = 16; sh > 0; sh >>= 1) s += __shfl_xor_sync(0xffffffffu, s, sh);
        if (lane == 0) g_red1[v] = s;
    } else if (v < 2064) {
        const float* row = g_p2T[v - 1040];
        float s = 0.f;
#pragma unroll
        for (int i = 0; i < 5; i++) {
            int idx = lane + i * 32;
            s += (idx < GRID) ? row[idx] : 0.f;
        }
#pragma unroll
        for (int sh = 16; sh > 0; sh >>= 1) s += __shfl_xor_sync(0xffffffffu, s, sh);
        if (lane == 0) g_red2[v - 1040] = s;
    } else if (v < 2080) {
        const int* row = g_pcntT[v - 2064];
        int s = 0;
#pragma unroll
        for (int i = 0; i < 4; i++) s += row[lane + i * 32];
#pragma unroll
        for (int sh = 16; sh > 0; sh >>= 1) s += __shfl_xor_sync(0xffffffffu, s, sh);
        if (lane == 0) g_redc[v - 2064] = (float)s;
    }
}

// ---------------- kfinal: stats + sim + class/bucket outputs ----------------
__device__ __forceinline__ bool gpred(int b, int l) {
    if (b == 0) return (l >= 1) && (l <= 8);
    if (b == 1) return (l >= 3) && (l <= 10);
    return ((l >= 1) && (l <= 2)) || ((l >= 9) && (l <= 10));
}

__global__ void kfinal(const int* __restrict__ labels, float* __restrict__ out) {
    __shared__ float s_mean[1024];
    __shared__ float s_Z[1024];
    __shared__ float s_cnt[16], s_nm[16], s_std[16];
    __shared__ float s_sim[256];
    __shared__ int s_lab[16];
    int tid = threadIdx.x;

    for (int v = tid; v < 1024; v += NTHR) {
        s_mean[v] = g_red1[v];
        s_Z[v] = g_red2[v];
    }
    if (tid >= 64 && tid < 80) s_lab[tid - 64] = labels[tid - 64];
    __syncthreads();

    if (tid < 16) {
        int k = tid;
        float counts = g_redc[k];
        float cnt = fmaxf(counts, 1.f);
        float inv = 1.f / cnt;
        float sa = 0.f, nm2 = 0.f;
        for (int c = 0; c < 64; c++) {
            float pcs = s_mean[k * 64 + c];
            sa += pcs;
            float m = pcs * inv;
            s_mean[k * 64 + c] = m;
            nm2 = fmaf(m, m, nm2);
        }
        s_nm[k] = sqrtf(nm2);
        s_cnt[k] = cnt;
        float ne = counts * 64.f;
        float ma = sa / fmaxf(ne, 1.f);
        float var = (g_red1[1024 + k] - ne * ma * ma) / fmaxf(ne - 1.f, 1.f);
        s_std[k] = sqrtf(fmaxf(var, 0.f));
    }
    __syncthreads();

    if (tid < 256) {
        int i = tid >> 4, j = tid & 15;
        float d = 0.f;
        for (int c = 0; c < 64; c++)
            d = fmaf(s_mean[i * 64 + c], s_Z[j * 64 + c], d);
        s_sim[tid] = d / (fmaxf(s_nm[i], 1e-20f) * s_cnt[j]);
    }
    __syncthreads();

    if (tid < NCLS) {
        int cl = tid;
        float cc = 0.f, inst = 0.f, cstd = 0.f, csim = 0.f;
        for (int k = 0; k < 16; k++) {
            if (s_lab[k] == cl) {
                cc += 1.f;
                inst += s_sim[k * 16 + k];
                cstd += s_std[k];
            }
        }
        for (int i = 0; i < 16; i++) {
            if (s_lab[i] != cl) continue;
            for (int j = 0; j < 16; j++)
                if (j != i && s_lab[j] == cl) csim += s_sim[i * 16 + j];
        }
        bool many = cc > 1.f;
        out[cl]      = many ? inst / fmaxf(cc, 1.f) : inst;
        out[11 + cl] = many ? csim / fmaxf(cc * (cc - 1.f), 1.f) : csim;
        out[25 + cl] = many ? cstd / fmaxf(cc, 1.f) : cstd;
    }
    if (tid >= 32 && tid < 35) {
        int b = tid - 32;
        float s = 0.f;
        int c = 0;
        for (int i = 0; i < 16; i++) {
            if (!gpred(b, s_lab[i])) continue;
            for (int j = 0; j < 16; j++) {
                if (s_lab[j] != s_lab[i] && gpred(b, s_lab[j])) {
                    c++;
                    s += s_sim[i * 16 + j];
                }
            }
        }
        out[22 + b] = (c > 1) ? s / (float)c : s;
    }
}

// ---------------- launcher ----------------
extern "C" void kernel_launch(void* const* d_in, const int* in_sizes, int n_in,
                              void* d_out, int out_size) {
    const float* v1     = (const float*)d_in[0];
    const float* v2     = (const float*)d_in[1];
    const int*   masks  = (const int*)d_in[2];
    const int*   labels = (const int*)d_in[3];
    float* out = (float*)d_out;

    kprep<<<GRIDP, NTHR>>>(masks);
    k1<<<GRID, NTHR>>>(v1);
    k4<<<GRID, NTHR>>>(v2);
    kred<<<130, NTHR>>>();
    kfinal<<<1, NTHR>>>(labels, out);
}

// round 12
// speedup vs baseline: 1.4131x; 1.0560x over previous
#include <cuda_runtime.h>
#include <math.h>

#define CCH   64
#define PIX   262144
#define NCLS  11
#define GRIDP 128
#define GRID  148
#define NTHR  512
#define NG    (PIX / 32)      // 8192 pixel groups of 32
#define ITER4 14              // 14*4 = 56 = ceil(NG/GRID)

// ---------------- device-global scratch (no allocation) ----------------
__device__ __align__(8) unsigned short g_pm[PIX];    // packed 16-bit instance masks
__device__ float g_invn[PIX];                        // 1/||X2_p||
__device__ int   g_pcntT[16][GRIDP];                 // counts, transposed
__device__ float g_p1T[1040][GRID];                  // transposed partials (pcs + sumsq)
__device__ float g_p2T[1024][GRID];                  // transposed Z partials
__device__ float g_red1[1040];
__device__ float g_red2[1024];
__device__ float g_redc[16];

// ---------------- f32x2 helpers ----------------
__device__ __forceinline__ unsigned long long pack2(float lo, float hi) {
    unsigned long long r;
    asm("mov.b64 %0, {%1, %2};" : "=l"(r) : "f"(lo), "f"(hi));
    return r;
}
__device__ __forceinline__ float2 unpack2(unsigned long long v) {
    float2 f;
    asm("mov.b64 {%0, %1}, %2;" : "=f"(f.x), "=f"(f.y) : "l"(v));
    return f;
}
__device__ __forceinline__ unsigned long long addf2(unsigned long long a, unsigned long long b) {
    unsigned long long r;
    asm("add.rn.f32x2 %0, %1, %2;" : "=l"(r) : "l"(a), "l"(b));
    return r;
}
__device__ __forceinline__ unsigned long long mulf2(unsigned long long a, unsigned long long b) {
    unsigned long long r;
    asm("mul.rn.f32x2 %0, %1, %2;" : "=l"(r) : "l"(a), "l"(b));
    return r;
}
__device__ __forceinline__ void macc3(unsigned long long &a01, unsigned long long &a23,
                                      float &q, unsigned long long x01, unsigned long long x23,
                                      float s2, unsigned b) {
    asm("{ .reg .pred p;\n\t"
        "setp.ne.u32 p, %6, 0;\n\t"
        "@p add.rn.f32x2 %0, %0, %3;\n\t"
        "@p add.rn.f32x2 %1, %1, %4;\n\t"
        "@p add.f32 %2, %2, %5; }"
        : "+l"(a01), "+l"(a23), "+f"(q)
        : "l"(x01), "l"(x23), "f"(s2), "r"(b));
}
__device__ __forceinline__ void macc2(unsigned long long &a01, unsigned long long &a23,
                                      unsigned long long x01, unsigned long long x23,
                                      unsigned b) {
    asm("{ .reg .pred p;\n\t"
        "setp.ne.u32 p, %4, 0;\n\t"
        "@p add.rn.f32x2 %0, %0, %2;\n\t"
        "@p add.rn.f32x2 %1, %1, %3; }"
        : "+l"(a01), "+l"(a23)
        : "l"(x01), "l"(x23), "r"(b));
}

// ---------------- kprep: pack masks + counts + X2 inverse norms ----------------
__global__ __launch_bounds__(NTHR, 1) void kprep(const int* __restrict__ masks,
                                                 const float* __restrict__ X2) {
    __shared__ int s_cnt[16][16];
    int tid = threadIdx.x, lane = tid & 31, w = tid >> 5;
    int q4 = blockIdx.x * NTHR + tid;   // quad index; GRIDP*NTHR == PIX/4 exactly

    // X2 inverse norms for this quad (deep unroll for MLP)
    {
        const float4* X2v = (const float4*)X2;
        float4 n2 = make_float4(0.f, 0.f, 0.f, 0.f);
#pragma unroll 16
        for (int c = 0; c < CCH; c++) {
            float4 x = X2v[(size_t)c * (PIX / 4) + q4];
            n2.x = fmaf(x.x, x.x, n2.x);
            n2.y = fmaf(x.y, x.y, n2.y);
            n2.z = fmaf(x.z, x.z, n2.z);
            n2.w = fmaf(x.w, x.w, n2.w);
        }
        float4 inv;
        inv.x = rsqrtf(n2.x); inv.y = rsqrtf(n2.y);
        inv.z = rsqrtf(n2.z); inv.w = rsqrtf(n2.w);
        ((float4*)g_invn)[q4] = inv;
    }

    const int4* m4 = (const int4*)masks;
    unsigned pm0 = 0, pm1 = 0, pm2 = 0, pm3 = 0;
    int cnt[16];
#pragma unroll
    for (int k = 0; k < 16; k++) {
        int4 v = m4[(size_t)k * (PIX / 4) + q4];
        pm0 |= (unsigned)v.x << k;
        pm1 |= (unsigned)v.y << k;
        pm2 |= (unsigned)v.z << k;
        pm3 |= (unsigned)v.w << k;
        cnt[k] = (v.x + v.y) + (v.z + v.w);
    }
    {
        ushort4 st;
        st.x = (unsigned short)pm0; st.y = (unsigned short)pm1;
        st.z = (unsigned short)pm2; st.w = (unsigned short)pm3;
        ((ushort4*)g_pm)[q4] = st;
    }
#pragma unroll
    for (int k = 0; k < 16; k++) {
#pragma unroll
        for (int s = 16; s > 0; s >>= 1)
            cnt[k] += __shfl_xor_sync(0xffffffffu, cnt[k], s);
    }
    if (lane < 16) s_cnt[w][lane] = cnt[lane];
    __syncthreads();
    if (tid < 16) {
        int s = 0;
#pragma unroll
        for (int w2 = 0; w2 < 16; w2++) s += s_cnt[w2][tid];
        g_pcntT[tid][blockIdx.x] = s;
    }
}

// ---------------- k1: masked per-channel sums of X1 + sumsq (depth-4 pipeline) ----
__global__ __launch_bounds__(NTHR, 1) void k1(const float* __restrict__ X1) {
    __shared__ float s_q[16][17];
    int tid = threadIdx.x, lane = tid & 31, w = tid >> 5;
    int cb = w * 4;

    unsigned long long a01[16], a23[16];
    float q[16];
#pragma unroll
    for (int k = 0; k < 16; k++) { a01[k] = 0ull; a23[k] = 0ull; q[k] = 0.f; }

    const float* b0 = X1 + (size_t)(cb + 0) * PIX;
    const float* b1 = X1 + (size_t)(cb + 1) * PIX;
    const float* b2 = X1 + (size_t)(cb + 2) * PIX;
    const float* b3 = X1 + (size_t)(cb + 3) * PIX;

#define LD1(G, PM, X0, X1r, X2r, X3r)                              \
    {                                                              \
        int gc = min((G), NG - 1);                                 \
        int p = gc * 32 + lane;                                    \
        PM = ((G) < NG) ? (unsigned)g_pm[p] : 0u;                  \
        X0 = b0[p]; X1r = b1[p]; X2r = b2[p]; X3r = b3[p];         \
    }
#define PROC1(PM, X0, X1r, X2r, X3r)                                        \
    {                                                                       \
        unsigned long long X01 = pack2(X0, X1r);                            \
        unsigned long long X23 = pack2(X2r, X3r);                           \
        float s2 = fmaf(X0, X0, fmaf(X1r, X1r, fmaf(X2r, X2r, X3r * X3r))); \
        _Pragma("unroll")                                                   \
        for (int k = 0; k < 16; k++)                                        \
            macc3(a01[k], a23[k], q[k], X01, X23, s2, PM & (1u << k));      \
    }
#define PHASE1(ST, OFF)                                                         \
    {                                                                           \
        unsigned pmc = pm##ST;                                                  \
        float c0 = ST##0, c1 = ST##1, c2 = ST##2, c3 = ST##3;                   \
        LD1(g + (OFF) * GRID, pm##ST, ST##0, ST##1, ST##2, ST##3);              \
        PROC1(pmc, c0, c1, c2, c3);                                             \
    }

    unsigned pmA, pmB, pmC, pmD;
    float A0, A1, A2, A3, B0, B1, B2, B3, C0, C1, C2, C3, D0, D1, D2, D3;
    int g = blockIdx.x;

    LD1(g + 0 * GRID, pmA, A0, A1, A2, A3);
    LD1(g + 1 * GRID, pmB, B0, B1, B2, B3);
    LD1(g + 2 * GRID, pmC, C0, C1, C2, C3);
    LD1(g + 3 * GRID, pmD, D0, D1, D2, D3);
#pragma unroll 1
    for (int it = 0; it < ITER4; it++) {
        PHASE1(A, 4)
        PHASE1(B, 5)
        PHASE1(C, 6)
        PHASE1(D, 7)
        g += 4 * GRID;
    }

#pragma unroll
    for (int k = 0; k < 16; k++) {
#pragma unroll
        for (int s = 16; s > 0; s >>= 1) {
            a01[k] = addf2(a01[k], __shfl_xor_sync(0xffffffffu, a01[k], s));
            a23[k] = addf2(a23[k], __shfl_xor_sync(0xffffffffu, a23[k], s));
            q[k] += __shfl_xor_sync(0xffffffffu, q[k], s);
        }
    }
    if (lane == 0) {
#pragma unroll
        for (int k = 0; k < 16; k++) {
            float2 u = unpack2(a01[k]), v = unpack2(a23[k]);
            g_p1T[k * 64 + cb + 0][blockIdx.x] = u.x;
            g_p1T[k * 64 + cb + 1][blockIdx.x] = u.y;
            g_p1T[k * 64 + cb + 2][blockIdx.x] = v.x;
            g_p1T[k * 64 + cb + 3][blockIdx.x] = v.y;
            s_q[w][k] = q[k];
        }
    }
    __syncthreads();
    if (tid < 16) {
        float s = 0.f;
#pragma unroll
        for (int w2 = 0; w2 < 16; w2++) s += s_q[w2][tid];
        g_p1T[1024 + tid][blockIdx.x] = s;
    }
}

// ---------------- k4: masked sums of normalized X2 (depth-4 pipeline, no barriers) -
__global__ __launch_bounds__(NTHR, 1) void k4(const float* __restrict__ X2) {
    int tid = threadIdx.x, lane = tid & 31, w = tid >> 5;
    int cb = w * 4;

    unsigned long long a01[16], a23[16];
#pragma unroll
    for (int k = 0; k < 16; k++) { a01[k] = 0ull; a23[k] = 0ull; }

    const float* b0 = X2 + (size_t)(cb + 0) * PIX;
    const float* b1 = X2 + (size_t)(cb + 1) * PIX;
    const float* b2 = X2 + (size_t)(cb + 2) * PIX;
    const float* b3 = X2 + (size_t)(cb + 3) * PIX;

#define LD2(G, PM, IV, X0, X1r, X2r, X3r)                          \
    {                                                              \
        int gc = min((G), NG - 1);                                 \
        int p = gc * 32 + lane;                                    \
        PM = ((G) < NG) ? (unsigned)g_pm[p] : 0u;                  \
        IV = g_invn[p];                                            \
        X0 = b0[p]; X1r = b1[p]; X2r = b2[p]; X3r = b3[p];         \
    }
#define PROC2(PM, IV, X0, X1r, X2r, X3r)                                    \
    {                                                                       \
        unsigned long long iv2 = pack2(IV, IV);                             \
        unsigned long long Y01 = mulf2(pack2(X0, X1r), iv2);                \
        unsigned long long Y23 = mulf2(pack2(X2r, X3r), iv2);               \
        _Pragma("unroll")                                                   \
        for (int k = 0; k < 16; k++)                                        \
            macc2(a01[k], a23[k], Y01, Y23, PM & (1u << k));                \
    }
#define PHASE2(ST, OFF)                                                           \
    {                                                                             \
        unsigned pmc = pm##ST; float ivc = iv##ST;                                \
        float c0 = ST##0, c1 = ST##1, c2 = ST##2, c3 = ST##3;                     \
        LD2(g + (OFF) * GRID, pm##ST, iv##ST, ST##0, ST##1, ST##2, ST##3);        \
        PROC2(pmc, ivc, c0, c1, c2, c3);                                          \
    }

    unsigned pmA, pmB, pmC, pmD;
    float ivA, ivB, ivC, ivD;
    float A0, A1, A2, A3, B0, B1, B2, B3, C0, C1, C2, C3, D0, D1, D2, D3;
    int g = blockIdx.x;

    LD2(g + 0 * GRID, pmA, ivA, A0, A1, A2, A3);
    LD2(g + 1 * GRID, pmB, ivB, B0, B1, B2, B3);
    LD2(g + 2 * GRID, pmC, ivC, C0, C1, C2, C3);
    LD2(g + 3 * GRID, pmD, ivD, D0, D1, D2, D3);
#pragma unroll 1
    for (int it = 0; it < ITER4; it++) {
        PHASE2(A, 4)
        PHASE2(B, 5)
        PHASE2(C, 6)
        PHASE2(D, 7)
        g += 4 * GRID;
    }

#pragma unroll
    for (int k = 0; k < 16; k++) {
#pragma unroll
        for (int s = 16; s > 0; s >>= 1) {
            a01[k] = addf2(a01[k], __shfl_xor_sync(0xffffffffu, a01[k], s));
            a23[k] = addf2(a23[k], __shfl_xor_sync(0xffffffffu, a23[k], s));
        }
    }
    if (lane == 0) {
#pragma unroll
        for (int k = 0; k < 16; k++) {
            float2 u = unpack2(a01[k]), v = unpack2(a23[k]);
            g_p2T[k * 64 + cb + 0][blockIdx.x] = u.x;
            g_p2T[k * 64 + cb + 1][blockIdx.x] = u.y;
            g_p2T[k * 64 + cb + 2][blockIdx.x] = v.x;
            g_p2T[k * 64 + cb + 3][blockIdx.x] = v.y;
        }
    }
}

// ---------------- kred: warp-per-value coalesced reduce ----------------
__global__ __launch_bounds__(NTHR, 1) void kred() {
    int lane = threadIdx.x & 31;
    int v = blockIdx.x * 16 + (threadIdx.x >> 5);   // <<<130,512>>> -> 2080 warps
    if (v < 1040) {
        const float* row = g_p1T[v];
        float s = 0.f;
#pragma unroll
        for (int i = 0; i < 5; i++) {
            int idx = lane + i * 32;
            s += (idx < GRID) ? row[idx] : 0.f;
        }
#pragma unroll
        for (int sh = 16; sh > 0; sh >>= 1) s += __shfl_xor_sync(0xffffffffu, s, sh);
        if (lane == 0) g_red1[v] = s;
    } else if (v < 2064) {
        const float* row = g_p2T[v - 1040];
        float s = 0.f;
#pragma unroll
        for (int i = 0; i < 5; i++) {
            int idx = lane + i * 32;
            s += (idx < GRID) ? row[idx] : 0.f;
        }
#pragma unroll
        for (int sh = 16; sh > 0; sh >>= 1) s += __shfl_xor_sync(0xffffffffu, s, sh);
        if (lane == 0) g_red2[v - 1040] = s;
    } else if (v < 2080) {
        const int* row = g_pcntT[v - 2064];
        int s = 0;
#pragma unroll
        for (int i = 0; i < 4; i++) s += row[lane + i * 32];
#pragma unroll
        for (int sh = 16; sh > 0; sh >>= 1) s += __shfl_xor_sync(0xffffffffu, s, sh);
        if (lane == 0) g_redc[v - 2064] = (float)s;
    }
}

// ---------------- kfinal: stats + sim + class/bucket outputs ----------------
__device__ __forceinline__ bool gpred(int b, int l) {
    if (b == 0) return (l >= 1) && (l <= 8);
    if (b == 1) return (l >= 3) && (l <= 10);
    return ((l >= 1) && (l <= 2)) || ((l >= 9) && (l <= 10));
}

__global__ void kfinal(const int* __restrict__ labels, float* __restrict__ out) {
    __shared__ float s_mean[1024];
    __shared__ float s_Z[1024];
    __shared__ float s_cnt[16], s_nm[16], s_std[16];
    __shared__ float s_sim[256];
    __shared__ int s_lab[16];
    int tid = threadIdx.x;

    for (int v = tid; v < 1024; v += NTHR) {
        s_mean[v] = g_red1[v];
        s_Z[v] = g_red2[v];
    }
    if (tid >= 64 && tid < 80) s_lab[tid - 64] = labels[tid - 64];
    __syncthreads();

    if (tid < 16) {
        int k = tid;
        float counts = g_redc[k];
        float cnt = fmaxf(counts, 1.f);
        float inv = 1.f / cnt;
        float sa = 0.f, nm2 = 0.f;
        for (int c = 0; c < 64; c++) {
            float pcs = s_mean[k * 64 + c];
            sa += pcs;
            float m = pcs * inv;
            s_mean[k * 64 + c] = m;
            nm2 = fmaf(m, m, nm2);
        }
        s_nm[k] = sqrtf(nm2);
        s_cnt[k] = cnt;
        float ne = counts * 64.f;
        float ma = sa / fmaxf(ne, 1.f);
        float var = (g_red1[1024 + k] - ne * ma * ma) / fmaxf(ne - 1.f, 1.f);
        s_std[k] = sqrtf(fmaxf(var, 0.f));
    }
    __syncthreads();

    if (tid < 256) {
        int i = tid >> 4, j = tid & 15;
        float d = 0.f;
        for (int c = 0; c < 64; c++)
            d = fmaf(s_mean[i * 64 + c], s_Z[j * 64 + c], d);
        s_sim[tid] = d / (fmaxf(s_nm[i], 1e-20f) * s_cnt[j]);
    }
    __syncthreads();

    if (tid < NCLS) {
        int cl = tid;
        float cc = 0.f, inst = 0.f, cstd = 0.f, csim = 0.f;
        for (int k = 0; k < 16; k++) {
            if (s_lab[k] == cl) {
                cc += 1.f;
                inst += s_sim[k * 16 + k];
                cstd += s_std[k];
            }
        }
        for (int i = 0; i < 16; i++) {
            if (s_lab[i] != cl) continue;
            for (int j = 0; j < 16; j++)
                if (j != i && s_lab[j] == cl) csim += s_sim[i * 16 + j];
        }
        bool many = cc > 1.f;
        out[cl]      = many ? inst / fmaxf(cc, 1.f) : inst;
        out[11 + cl] = many ? csim / fmaxf(cc * (cc - 1.f), 1.f) : csim;
        out[25 + cl] = many ? cstd / fmaxf(cc, 1.f) : cstd;
    }
    if (tid >= 32 && tid < 35) {
        int b = tid - 32;
        float s = 0.f;
        int c = 0;
        for (int i = 0; i < 16; i++) {
            if (!gpred(b, s_lab[i])) continue;
            for (int j = 0; j < 16; j++) {
                if (s_lab[j] != s_lab[i] && gpred(b, s_lab[j])) {
                    c++;
                    s += s_sim[i * 16 + j];
                }
            }
        }
        out[22 + b] = (c > 1) ? s / (float)c : s;
    }
}

// ---------------- launcher ----------------
extern "C" void kernel_launch(void* const* d_in, const int* in_sizes, int n_in,
                              void* d_out, int out_size) {
    const float* v1     = (const float*)d_in[0];
    const float* v2     = (const float*)d_in[1];
    const int*   masks  = (const int*)d_in[2];
    const int*   labels = (const int*)d_in[3];
    float* out = (float*)d_out;

    kprep<<<GRIDP, NTHR>>>(masks, v2);
    k1<<<GRID, NTHR>>>(v1);
    k4<<<GRID, NTHR>>>(v2);
    kred<<<130, NTHR>>>();
    kfinal<<<1, NTHR>>>(labels, out);
}